// round 1
// baseline (speedup 1.0000x reference)
#include <cuda_runtime.h>
#include <math.h>

// Problem constants (ContLoss: T=512, B=64, E=1024, N=128)
#define TT   512
#define BZ   64
#define EE   1024
#define NNEG 128
#define EPSV 1e-8f
// 1/TEMP with TEMP=0.1
#define INV_TEMP 10.0f

// per-t partial losses (scratch; __device__ global is the allowed scratch path)
__device__ float g_partial[TT];

// One CTA per t. 256 threads; thread tid owns elements [4*tid, 4*tid+4).
__global__ __launch_bounds__(256) void contloss_main(
    const int*   __restrict__ index,
    const float* __restrict__ z1,
    const float* __restrict__ z2,
    const int*   __restrict__ neg_s,
    const int*   __restrict__ neg_w)
{
    const int t   = blockIdx.x;
    const int tid = threadIdx.x;

    __shared__ int sh_s[NNEG];
    __shared__ int sh_w[NNEG];
    if (tid < NNEG) {
        sh_s[tid] = neg_s[t * NNEG + tid];
        sh_w[tid] = neg_w[t * NNEG + tid];
    }
    __syncthreads();

    // accumulate sum and sum-of-squares over the 128 negative rows
    float s0 = 0.f, s1 = 0.f, s2 = 0.f, s3 = 0.f;
    float q0 = 0.f, q1 = 0.f, q2 = 0.f, q3 = 0.f;

    #pragma unroll 4
    for (int n = 0; n < NNEG; ++n) {
        const size_t row = (size_t)sh_s[n] * BZ + (size_t)sh_w[n];
        const float4 v = __ldg((const float4*)(z1 + row * EE) + tid);
        s0 += v.x; s1 += v.y; s2 += v.z; s3 += v.w;
        q0 += v.x * v.x; q1 += v.y * v.y; q2 += v.z * v.z; q3 += v.w * v.w;
    }

    // anchor (orig) and positive (adv) rows
    const int bidx = index[t];
    const size_t arow = (size_t)t * BZ + (size_t)bidx;
    const float4 vo = __ldg((const float4*)(z1 + arow * EE) + tid);
    const float4 va = __ldg((const float4*)(z2 + arow * EE) + tid);

    const float sqrtN = sqrtf((float)NNEG);

    // per-feature negative cosine -> exp, plus positive cosine pieces
    float den = 0.f, dotp = 0.f, na2 = 0.f, nb2 = 0.f;

    {
        float o, sm, qq;
        o = vo.x; sm = s0; qq = q0;
        den += expf((o * sm) / (fmaxf(sqrtf(qq), EPSV) * fmaxf(sqrtN * fabsf(o), EPSV)) * INV_TEMP);
        o = vo.y; sm = s1; qq = q1;
        den += expf((o * sm) / (fmaxf(sqrtf(qq), EPSV) * fmaxf(sqrtN * fabsf(o), EPSV)) * INV_TEMP);
        o = vo.z; sm = s2; qq = q2;
        den += expf((o * sm) / (fmaxf(sqrtf(qq), EPSV) * fmaxf(sqrtN * fabsf(o), EPSV)) * INV_TEMP);
        o = vo.w; sm = s3; qq = q3;
        den += expf((o * sm) / (fmaxf(sqrtf(qq), EPSV) * fmaxf(sqrtN * fabsf(o), EPSV)) * INV_TEMP);
    }
    dotp = vo.x * va.x + vo.y * va.y + vo.z * va.z + vo.w * va.w;
    na2  = vo.x * vo.x + vo.y * vo.y + vo.z * vo.z + vo.w * vo.w;
    nb2  = va.x * va.x + va.y * va.y + va.z * va.z + va.w * va.w;

    // block reduction (fixed order -> deterministic)
    const int lane = tid & 31;
    const int warp = tid >> 5;
    #pragma unroll
    for (int off = 16; off > 0; off >>= 1) {
        den  += __shfl_down_sync(0xffffffffu, den,  off);
        dotp += __shfl_down_sync(0xffffffffu, dotp, off);
        na2  += __shfl_down_sync(0xffffffffu, na2,  off);
        nb2  += __shfl_down_sync(0xffffffffu, nb2,  off);
    }
    __shared__ float r_den[8], r_dot[8], r_na[8], r_nb[8];
    if (lane == 0) {
        r_den[warp] = den; r_dot[warp] = dotp; r_na[warp] = na2; r_nb[warp] = nb2;
    }
    __syncthreads();
    if (tid == 0) {
        float D = 0.f, P = 0.f, A = 0.f, Bv = 0.f;
        #pragma unroll
        for (int w = 0; w < 8; ++w) { D += r_den[w]; P += r_dot[w]; A += r_na[w]; Bv += r_nb[w]; }
        const float pos_cos = P / (fmaxf(sqrtf(A), EPSV) * fmaxf(sqrtf(Bv), EPSV));
        g_partial[t] = logf(D) - pos_cos * INV_TEMP;
    }
}

// Deterministic tree reduction of the 512 per-t partials into the scalar loss.
__global__ void contloss_reduce(float* __restrict__ out)
{
    __shared__ float sh[TT];
    const int tid = threadIdx.x;
    sh[tid] = g_partial[tid];
    __syncthreads();
    #pragma unroll
    for (int s = TT / 2; s > 0; s >>= 1) {
        if (tid < s) sh[tid] += sh[tid + s];
        __syncthreads();
    }
    if (tid == 0) out[0] = sh[0];
}

extern "C" void kernel_launch(void* const* d_in, const int* in_sizes, int n_in,
                              void* d_out, int out_size)
{
    const int*   index = (const int*)  d_in[0];
    const float* z1    = (const float*)d_in[1];
    const float* z2    = (const float*)d_in[2];
    const int*   ns    = (const int*)  d_in[3];
    const int*   nw    = (const int*)  d_in[4];

    contloss_main<<<TT, 256>>>(index, z1, z2, ns, nw);
    contloss_reduce<<<1, TT>>>((float*)d_out);
}

// round 2
// speedup vs baseline: 1.2225x; 1.2225x over previous
#include <cuda_runtime.h>
#include <math.h>

// Problem constants (ContLoss: T=512, B=64, E=1024, N=128)
#define TT   512
#define BZ   64
#define EE   1024
#define NNEG 128
#define EPSV 1e-8f
#define INV_TEMP 10.0f   // 1/TEMP, TEMP=0.1

// scratch: per-t partial losses + completion counter (zero-initialized)
__device__ float g_partial[TT];
__device__ unsigned int g_count;

// One CTA per t. 256 threads; thread tid owns float4 column slice tid.
__global__ __launch_bounds__(256) void contloss_fused(
    const int*   __restrict__ index,
    const float* __restrict__ z1,
    const float* __restrict__ z2,
    const int*   __restrict__ neg_s,
    const int*   __restrict__ neg_w,
    float*       __restrict__ out)
{
    const int t   = blockIdx.x;
    const int tid = threadIdx.x;

    // Precompute row offsets (in float4 units) for the 128 negatives: one LDS per n in the hot loop.
    __shared__ int sh_off[NNEG];
    if (tid < NNEG) {
        const int s = neg_s[t * NNEG + tid];
        const int w = neg_w[t * NNEG + tid];
        sh_off[tid] = (s * BZ + w) * (EE / 4);
    }
    __syncthreads();

    const float4* __restrict__ z1v = (const float4*)z1;

    // accumulate sum and sum-of-squares over the 128 negative rows
    float s0 = 0.f, s1 = 0.f, s2 = 0.f, s3 = 0.f;
    float q0 = 0.f, q1 = 0.f, q2 = 0.f, q3 = 0.f;

    #pragma unroll 8
    for (int n = 0; n < NNEG; ++n) {
        const float4 v = __ldg(z1v + sh_off[n] + tid);
        s0 += v.x; s1 += v.y; s2 += v.z; s3 += v.w;
        q0 = fmaf(v.x, v.x, q0); q1 = fmaf(v.y, v.y, q1);
        q2 = fmaf(v.z, v.z, q2); q3 = fmaf(v.w, v.w, q3);
    }

    // anchor (orig) and positive (adv) rows
    const int bidx = index[t];
    const int arow4 = (t * BZ + bidx) * (EE / 4);
    const float4 vo = __ldg(z1v + arow4 + tid);
    const float4 va = __ldg((const float4*)z2 + arow4 + tid);

    const float sqrtN = sqrtf((float)NNEG);

    float den = 0.f;
    {
        float o, sm, qq;
        o = vo.x; sm = s0; qq = q0;
        den += expf((o * sm) / (fmaxf(sqrtf(qq), EPSV) * fmaxf(sqrtN * fabsf(o), EPSV)) * INV_TEMP);
        o = vo.y; sm = s1; qq = q1;
        den += expf((o * sm) / (fmaxf(sqrtf(qq), EPSV) * fmaxf(sqrtN * fabsf(o), EPSV)) * INV_TEMP);
        o = vo.z; sm = s2; qq = q2;
        den += expf((o * sm) / (fmaxf(sqrtf(qq), EPSV) * fmaxf(sqrtN * fabsf(o), EPSV)) * INV_TEMP);
        o = vo.w; sm = s3; qq = q3;
        den += expf((o * sm) / (fmaxf(sqrtf(qq), EPSV) * fmaxf(sqrtN * fabsf(o), EPSV)) * INV_TEMP);
    }
    float dotp = vo.x * va.x + vo.y * va.y + vo.z * va.z + vo.w * va.w;
    float na2  = vo.x * vo.x + vo.y * vo.y + vo.z * vo.z + vo.w * vo.w;
    float nb2  = va.x * va.x + va.y * va.y + va.z * va.z + va.w * va.w;

    // block reduction (fixed order -> deterministic)
    const int lane = tid & 31;
    const int warp = tid >> 5;
    #pragma unroll
    for (int off = 16; off > 0; off >>= 1) {
        den  += __shfl_down_sync(0xffffffffu, den,  off);
        dotp += __shfl_down_sync(0xffffffffu, dotp, off);
        na2  += __shfl_down_sync(0xffffffffu, na2,  off);
        nb2  += __shfl_down_sync(0xffffffffu, nb2,  off);
    }
    __shared__ float r_den[8], r_dot[8], r_na[8], r_nb[8];
    __shared__ bool sh_last;
    if (lane == 0) {
        r_den[warp] = den; r_dot[warp] = dotp; r_na[warp] = na2; r_nb[warp] = nb2;
    }
    __syncthreads();
    if (tid == 0) {
        float D = 0.f, P = 0.f, A = 0.f, Bv = 0.f;
        #pragma unroll
        for (int w = 0; w < 8; ++w) { D += r_den[w]; P += r_dot[w]; A += r_na[w]; Bv += r_nb[w]; }
        const float pos_cos = P / (fmaxf(sqrtf(A), EPSV) * fmaxf(sqrtf(Bv), EPSV));
        g_partial[t] = logf(D) - pos_cos * INV_TEMP;
        __threadfence();
        const unsigned int done = atomicAdd(&g_count, 1u);
        sh_last = (done == (unsigned int)(gridDim.x - 1));
    }
    __syncthreads();

    // last CTA to finish does the deterministic final reduction
    if (sh_last) {
        __shared__ float sh[256];
        sh[tid] = g_partial[tid] + g_partial[tid + 256];
        __syncthreads();
        #pragma unroll
        for (int s = 128; s > 0; s >>= 1) {
            if (tid < s) sh[tid] += sh[tid + s];
            __syncthreads();
        }
        if (tid == 0) {
            out[0] = sh[0];
            g_count = 0u;  // reset for next graph replay
        }
    }
}

extern "C" void kernel_launch(void* const* d_in, const int* in_sizes, int n_in,
                              void* d_out, int out_size)
{
    const int*   index = (const int*)  d_in[0];
    const float* z1    = (const float*)d_in[1];
    const float* z2    = (const float*)d_in[2];
    const int*   ns    = (const int*)  d_in[3];
    const int*   nw    = (const int*)  d_in[4];

    contloss_fused<<<TT, 256>>>(index, z1, z2, ns, nw, (float*)d_out);
}